// round 3
// baseline (speedup 1.0000x reference)
#include <cuda_runtime.h>
#include <math.h>

#define Bb   32
#define Nn   4096
#define Dd   256
#define Kk   128
#define Dc   64

// ---------------- scratch (no allocs allowed) ----------------
__device__ float g_sq[(size_t)Bb * Nn * Dc];      // 32 MB
__device__ float g_assign[(size_t)Bb * Nn * Kk];  // 64 MB
__device__ float g_agg[(size_t)Bb * Kk * Dc];     // 1 MB
__device__ float g_mass[(size_t)Bb * Kk];

// ---------------- init ----------------
__global__ void __launch_bounds__(256) k_init() {
    int i = blockIdx.x * blockDim.x + threadIdx.x;
    if (i < Bb * Kk) g_mass[i] = 0.0f;
    if (i < Bb * Kk * Dc) g_agg[i] = 0.0f;
}

// ---------------- squeeze MLP: X(64tok x 256) -> h(64x64) -> sq(64x64) ----------------
// 256 threads (16x16), 4x4 micro-tile, smem tiles padded to stride 68 (16B aligned rows).
__global__ void __launch_bounds__(256) k_squeeze(
    const float* __restrict__ X, const float* __restrict__ W1,
    const float* __restrict__ b1v, const float* __restrict__ W2,
    const float* __restrict__ b2v)
{
    __shared__ float smem[8704];              // 2 * 64*68 floats
    float* Xs  = smem;                        // phase1: [32][68] (d-major, token cols)
    float* Ws  = smem + 32 * 68;              // phase1: [32][68] (d-major, e cols)
    float* Hs  = smem;                        // phase2: [64 e][68 tok]
    float* W2s = smem + 64 * 68;              // phase2: [64 e][68 f]

    const int tid = threadIdx.x;
    const int tx = tid & 15, ty = tid >> 4;
    const int bn0 = blockIdx.x * 64;
    const int r0 = ty * 4;   // token
    const int c0 = tx * 4;   // e / f

    float acc[4][4] = {};
    for (int d0 = 0; d0 < Dd; d0 += 32) {
        #pragma unroll
        for (int l = 0; l < 8; l++) {
            int i = tid + l * 256;           // 0..2047
            int row = i >> 5, dd = i & 31;
            Xs[dd * 68 + row] = X[(size_t)(bn0 + row) * Dd + d0 + dd];
            Ws[dd * 68 + row] = W1[row * Dd + d0 + dd];
        }
        __syncthreads();
        #pragma unroll
        for (int kk = 0; kk < 32; kk++) {
            float4 a4 = *(const float4*)&Xs[kk * 68 + r0];
            float4 b4 = *(const float4*)&Ws[kk * 68 + c0];
            float av[4] = {a4.x, a4.y, a4.z, a4.w};
            float bv[4] = {b4.x, b4.y, b4.z, b4.w};
            #pragma unroll
            for (int i = 0; i < 4; i++)
                #pragma unroll
                for (int j = 0; j < 4; j++) acc[i][j] += av[i] * bv[j];
        }
        __syncthreads();
    }

    // epilogue 1: bias + LeakyReLU, store h transposed [e][tok]
    {
        float bb[4];
        #pragma unroll
        for (int j = 0; j < 4; j++) bb[j] = __ldg(&b1v[c0 + j]);
        #pragma unroll
        for (int i = 0; i < 4; i++)
            #pragma unroll
            for (int j = 0; j < 4; j++) {
                float h = acc[i][j] + bb[j];
                h = (h >= 0.0f) ? h : 0.01f * h;
                Hs[(c0 + j) * 68 + (r0 + i)] = h;
            }
    }
    // load W2 transposed [e][f]
    #pragma unroll
    for (int l = 0; l < 16; l++) {
        int i = tid + l * 256;               // 0..4095
        int f = i >> 6, e = i & 63;
        W2s[e * 68 + f] = W2[f * Dc + e];
    }
    __syncthreads();

    float acc2[4][4] = {};
    #pragma unroll 16
    for (int e = 0; e < Dc; e++) {
        float4 a4 = *(const float4*)&Hs[e * 68 + r0];
        float4 b4 = *(const float4*)&W2s[e * 68 + c0];
        float av[4] = {a4.x, a4.y, a4.z, a4.w};
        float bv[4] = {b4.x, b4.y, b4.z, b4.w};
        #pragma unroll
        for (int i = 0; i < 4; i++)
            #pragma unroll
            for (int j = 0; j < 4; j++) acc2[i][j] += av[i] * bv[j];
    }
    {
        float bb[4];
        #pragma unroll
        for (int j = 0; j < 4; j++) bb[j] = __ldg(&b2v[c0 + j]);
        #pragma unroll
        for (int i = 0; i < 4; i++)
            #pragma unroll
            for (int j = 0; j < 4; j++)
                g_sq[(size_t)(bn0 + r0 + i) * Dc + c0 + j] = acc2[i][j] + bb[j];
    }
}

// ---------------- assign: logits(64tok x 128K) -> softmax -> g_assign, partial mass ----------------
__global__ void __launch_bounds__(256) k_assign(
    const float* __restrict__ X, const float* __restrict__ Wa,
    const float* __restrict__ bav)
{
    __shared__ float smem[8448 + 64];
    float* Xs    = smem;               // phase1 [32][68]   (2176)
    float* Was   = smem + 2176;        // phase1 [32][132]  (4224)
    float* ls    = smem;               // phase2 [64][132]  (8448)
    float* rowis = smem + 8448;        // [64] 1/rowsum

    const int tid = threadIdx.x;
    const int tx = tid & 15, ty = tid >> 4;
    const int bn0 = blockIdx.x * 64;
    const int b = bn0 >> 12;           // N = 4096
    const int t0 = ty * 4;             // token
    const int k0 = tx * 8;             // cluster k

    float acc[4][8] = {};
    for (int d0 = 0; d0 < Dd; d0 += 32) {
        #pragma unroll
        for (int l = 0; l < 8; l++) {
            int i = tid + l * 256;
            int row = i >> 5, dd = i & 31;
            Xs[dd * 68 + row] = X[(size_t)(bn0 + row) * Dd + d0 + dd];
        }
        #pragma unroll
        for (int l = 0; l < 16; l++) {
            int i = tid + l * 256;       // 0..4095
            int k = i >> 5, dd = i & 31;
            Was[dd * 132 + k] = Wa[k * Dd + d0 + dd];
        }
        __syncthreads();
        #pragma unroll
        for (int kk = 0; kk < 32; kk++) {
            float4 a4 = *(const float4*)&Xs[kk * 68 + t0];
            float4 b0 = *(const float4*)&Was[kk * 132 + k0];
            float4 b1 = *(const float4*)&Was[kk * 132 + k0 + 4];
            float av[4] = {a4.x, a4.y, a4.z, a4.w};
            float bv[8] = {b0.x, b0.y, b0.z, b0.w, b1.x, b1.y, b1.z, b1.w};
            #pragma unroll
            for (int i = 0; i < 4; i++)
                #pragma unroll
                for (int j = 0; j < 8; j++) acc[i][j] += av[i] * bv[j];
        }
        __syncthreads();
    }

    // logits (+bias) into smem
    {
        float bb[8];
        #pragma unroll
        for (int j = 0; j < 8; j++) bb[j] = __ldg(&bav[k0 + j]);
        #pragma unroll
        for (int i = 0; i < 4; i++)
            #pragma unroll
            for (int j = 0; j < 8; j++)
                ls[(t0 + i) * 132 + (k0 + j)] = acc[i][j] + bb[j];
    }
    __syncthreads();

    // per-row softmax (one thread per token row)
    if (tid < 64) {
        float m = -1e30f;
        #pragma unroll 8
        for (int k = 0; k < Kk; k++) m = fmaxf(m, ls[tid * 132 + k]);
        float s = 0.0f;
        #pragma unroll 8
        for (int k = 0; k < Kk; k++) {
            float e = expf(ls[tid * 132 + k] - m);
            ls[tid * 132 + k] = e;
            s += e;
        }
        rowis[tid] = 1.0f / s;
    }
    __syncthreads();

    // normalize, write to global
    for (int i = tid; i < 64 * Kk; i += 256) {
        int t = i >> 7, k = i & 127;
        float v = ls[t * 132 + k] * rowis[t];
        ls[t * 132 + k] = v;
        g_assign[(size_t)(bn0 + t) * Kk + k] = v;
    }
    __syncthreads();

    // partial mass
    if (tid < Kk) {
        float s = 0.0f;
        #pragma unroll 8
        for (int t = 0; t < 64; t++) s += ls[t * 132 + tid];
        atomicAdd(&g_mass[b * Kk + tid], s);
    }
}

// ---------------- agg: agg[b,k,d] += sum_n assign[b,n,k]*sq[b,n,d], split over N ----------------
__global__ void __launch_bounds__(256) k_agg()
{
    __shared__ float As[32 * 132];   // [tok][k]
    __shared__ float Bs[32 * 68];    // [tok][d]

    const int tid = threadIdx.x;
    const int tx = tid & 15, ty = tid >> 4;
    const int b = blockIdx.x;
    const int n0 = blockIdx.y * 256;
    const int k0 = ty * 8;
    const int d0 = tx * 4;

    float acc[8][4] = {};
    for (int nt = 0; nt < 256; nt += 32) {
        const size_t base = (size_t)(b * Nn + n0 + nt);
        #pragma unroll
        for (int l = 0; l < 16; l++) {
            int i = tid + l * 256;       // 0..4095
            int tok = i >> 7, k = i & 127;
            As[tok * 132 + k] = g_assign[(base + tok) * Kk + k];
        }
        #pragma unroll
        for (int l = 0; l < 8; l++) {
            int i = tid + l * 256;       // 0..2047
            int tok = i >> 6, d = i & 63;
            Bs[tok * 68 + d] = g_sq[(base + tok) * Dc + d];
        }
        __syncthreads();
        #pragma unroll
        for (int kk = 0; kk < 32; kk++) {
            float4 a0 = *(const float4*)&As[kk * 132 + k0];
            float4 a1 = *(const float4*)&As[kk * 132 + k0 + 4];
            float4 b4 = *(const float4*)&Bs[kk * 68 + d0];
            float av[8] = {a0.x, a0.y, a0.z, a0.w, a1.x, a1.y, a1.z, a1.w};
            float bv[4] = {b4.x, b4.y, b4.z, b4.w};
            #pragma unroll
            for (int i = 0; i < 8; i++)
                #pragma unroll
                for (int j = 0; j < 4; j++) acc[i][j] += av[i] * bv[j];
        }
        __syncthreads();
    }
    #pragma unroll
    for (int i = 0; i < 8; i++)
        #pragma unroll
        for (int j = 0; j < 4; j++)
            atomicAdd(&g_agg[(size_t)b * (Kk * Dc) + (k0 + i) * Dc + d0 + j], acc[i][j]);
}

// ---------------- finalize: vlad = agg - mass*centroid, L2-normalize per batch ----------------
__global__ void __launch_bounds__(256) k_final(
    const float* __restrict__ centroid, float* __restrict__ out)
{
    __shared__ float red[256];
    __shared__ float s_inv;
    const int b = blockIdx.x;
    const int tid = threadIdx.x;

    float ss = 0.0f;
    for (int i = tid; i < Kk * Dc; i += 256) {
        int k = i >> 6;
        float v = g_agg[(size_t)b * (Kk * Dc) + i] - g_mass[b * Kk + k] * __ldg(&centroid[i]);
        out[(size_t)b * (Kk * Dc) + i] = v;
        ss += v * v;
    }
    red[tid] = ss;
    __syncthreads();
    #pragma unroll
    for (int s = 128; s > 0; s >>= 1) {
        if (tid < s) red[tid] += red[tid + s];
        __syncthreads();
    }
    if (tid == 0) {
        float n = sqrtf(red[0]);
        s_inv = 1.0f / fmaxf(n, 1e-12f);
    }
    __syncthreads();
    float inv = s_inv;
    for (int i = tid; i < Kk * Dc; i += 256) out[(size_t)b * (Kk * Dc) + i] *= inv;
}

// ---------------- launch ----------------
extern "C" void kernel_launch(void* const* d_in, const int* in_sizes, int n_in,
                              void* d_out, int out_size)
{
    const float* X        = (const float*)d_in[0];
    const float* W1       = (const float*)d_in[1];
    const float* b1       = (const float*)d_in[2];
    const float* W2       = (const float*)d_in[3];
    const float* b2       = (const float*)d_in[4];
    const float* Wa       = (const float*)d_in[5];
    const float* ba       = (const float*)d_in[6];
    const float* centroid = (const float*)d_in[7];
    float* out = (float*)d_out;

    k_init<<<1024, 256>>>();
    k_squeeze<<<(Bb * Nn) / 64, 256>>>(X, W1, b1, W2, b2);
    k_assign<<<(Bb * Nn) / 64, 256>>>(X, Wa, ba);
    dim3 g3(Bb, 16);
    k_agg<<<g3, 256>>>();
    k_final<<<Bb, 256>>>(centroid, out);
}

// round 5
// speedup vs baseline: 1.4830x; 1.4830x over previous
#include <cuda_runtime.h>
#include <math.h>
#include <stdint.h>

#define Bb 32
#define Nn 4096
#define Dd 256
#define Kk 128
#define Dc 64

// ---------------- device scratch ----------------
__device__ float g_agg[(size_t)Bb * Kk * Dc];
__device__ float g_mass[Bb * Kk];

// ---------------- smem layout (float offsets) ----------------
#define XS   260                 // Xs stride (floats)
#define WS   68                  // W chunk / W2 stride
#define YS   132                 // Ys / As / Bs3 stride
#define OFF_AS   0               // assign^T [128 cluster][132] : 16896 floats
#define OFF_BS3  16896           // sq^T     [64 d][132]        : 8448
#define OFF_YS   25344           // Y        [192 col][132]     : 25344
#define OFF_W2S  50688           // W2       [64 f][68]         : 4352
#define OFF_XS   0               // stage-1 alias: X [128][260] : 33280
#define OFF_WS   33280           // stage-1 alias: W chunk [192][68] : 13056
#define SMEM_FLOATS 55040        // 220160 bytes

// ---------------- helpers ----------------
__device__ __forceinline__ uint32_t f2tf(float x) {
    uint32_t r;
    asm("cvt.rna.tf32.f32 %0, %1;" : "=r"(r) : "f"(x));
    return r;
}
__device__ __forceinline__ void split_tf(float x, uint32_t& hi, uint32_t& lo) {
    hi = f2tf(x);
    lo = f2tf(x - __uint_as_float(hi));
}
__device__ __forceinline__ void mma8(float* d, const uint32_t* a, const uint32_t* b) {
    asm volatile(
        "mma.sync.aligned.m16n8k8.row.col.f32.tf32.tf32.f32 "
        "{%0,%1,%2,%3}, {%4,%5,%6,%7}, {%8,%9}, {%0,%1,%2,%3};"
        : "+f"(d[0]), "+f"(d[1]), "+f"(d[2]), "+f"(d[3])
        : "r"(a[0]), "r"(a[1]), "r"(a[2]), "r"(a[3]), "r"(b[0]), "r"(b[1]));
}

// ---------------- init ----------------
__global__ void __launch_bounds__(256) k_init() {
    int i = blockIdx.x * 256 + threadIdx.x;
    if (i < Bb * Kk * Dc) g_agg[i] = 0.0f;
    else if (i < Bb * Kk * Dc + Bb * Kk) g_mass[i - Bb * Kk * Dc] = 0.0f;
}

// ---------------- fused main kernel: one 128-token tile per block ----------------
__global__ void __launch_bounds__(256, 1) k_fused(
    const float* __restrict__ X,  const float* __restrict__ W1,
    const float* __restrict__ b1, const float* __restrict__ W2,
    const float* __restrict__ b2, const float* __restrict__ Wa,
    const float* __restrict__ ba)
{
    extern __shared__ float sm[];
    __shared__ float s_ba[128], s_b1[64], s_b2[64];

    const int tid  = threadIdx.x;
    const int w    = tid >> 5;
    const int lane = tid & 31;
    const int ty   = lane >> 2;        // 0..7
    const int tx   = lane & 3;         // 0..3
    const int b    = blockIdx.x >> 5;
    const int n0t  = (blockIdx.x & 31) * 128;

    if (tid < 128) s_ba[tid] = ba[tid];
    else if (tid < 192) s_b1[tid - 128] = b1[tid - 128];
    else s_b2[tid - 192] = b2[tid - 192];

    // ---- load X tile (128 x 256) and W2 (64 x 64) into smem ----
    {
        const float4* X4 = (const float4*)(X + (size_t)(b * Nn + n0t) * Dd);
        #pragma unroll
        for (int it = 0; it < 32; it++) {
            int idx = tid + it * 256;              // 0..8191 float4s
            int row = idx >> 6, c4 = idx & 63;
            float4 v = X4[(size_t)row * 64 + c4];
            *(float4*)&sm[OFF_XS + row * XS + c4 * 4] = v;
        }
        const float4* W24 = (const float4*)W2;
        #pragma unroll
        for (int it = 0; it < 4; it++) {
            int idx = tid + it * 256;              // 0..1023
            int row = idx >> 4, c4 = idx & 15;
            *(float4*)&sm[OFF_W2S + row * WS + c4 * 4] = W24[row * 16 + c4];
        }
    }
    __syncthreads();

    // ---- stage 1: Y[128 tok, 192] = X @ [Wa;W1]^T ----
    const int wm = (w & 3) * 32;       // token block
    const int wn = (w >> 2) * 96;      // output-col block
    float acc1[2][12][4];
    #pragma unroll
    for (int mt = 0; mt < 2; mt++)
        #pragma unroll
        for (int nb = 0; nb < 12; nb++)
            #pragma unroll
            for (int q = 0; q < 4; q++) acc1[mt][nb][q] = 0.0f;

    for (int c = 0; c < 4; c++) {
        // load W chunk: rows 0..191 = [Wa;W1], cols c*64..c*64+63
        #pragma unroll
        for (int it = 0; it < 12; it++) {
            int idx = tid + it * 256;              // 0..3071 float4s
            int row = idx >> 4, c4 = idx & 15;
            const float* src = (row < 128) ? (Wa + (size_t)row * Dd)
                                           : (W1 + (size_t)(row - 128) * Dd);
            *(float4*)&sm[OFF_WS + row * WS + c4 * 4] =
                *(const float4*)(src + c * 64 + c4 * 4);
        }
        __syncthreads();

        #pragma unroll
        for (int k8 = 0; k8 < 8; k8++) {
            const int kk = c * 64 + k8 * 8;        // col within Xs
            uint32_t ah[2][4], al[2][4];
            #pragma unroll
            for (int mt = 0; mt < 2; mt++) {
                int base = OFF_XS + (wm + mt * 16 + ty) * XS + kk + tx;
                split_tf(sm[base],            ah[mt][0], al[mt][0]);
                split_tf(sm[base + 8 * XS],   ah[mt][1], al[mt][1]);
                split_tf(sm[base + 4],        ah[mt][2], al[mt][2]);
                split_tf(sm[base + 8 * XS + 4], ah[mt][3], al[mt][3]);
            }
            uint32_t bh[12][2], bl[12][2];
            #pragma unroll
            for (int nb = 0; nb < 12; nb++) {
                int baseb = OFF_WS + (wn + nb * 8 + ty) * WS + k8 * 8 + tx;
                split_tf(sm[baseb],     bh[nb][0], bl[nb][0]);
                split_tf(sm[baseb + 4], bh[nb][1], bl[nb][1]);
            }
            #pragma unroll
            for (int mt = 0; mt < 2; mt++)
                #pragma unroll
                for (int nb = 0; nb < 12; nb++) {
                    mma8(acc1[mt][nb], ah[mt], bh[nb]);
                    mma8(acc1[mt][nb], ah[mt], bl[nb]);
                    mma8(acc1[mt][nb], al[mt], bh[nb]);
                }
        }
        __syncthreads();
    }

    // ---- write Y column-major [col][tok] ----
    #pragma unroll
    for (int mt = 0; mt < 2; mt++)
        #pragma unroll
        for (int nb = 0; nb < 12; nb++) {
            int row = wm + mt * 16 + ty;
            int col = wn + nb * 8 + 2 * tx;
            sm[OFF_YS + col * YS + row]           = acc1[mt][nb][0];
            sm[OFF_YS + (col + 1) * YS + row]     = acc1[mt][nb][1];
            sm[OFF_YS + col * YS + row + 8]       = acc1[mt][nb][2];
            sm[OFF_YS + (col + 1) * YS + row + 8] = acc1[mt][nb][3];
        }
    __syncthreads();

    // ---- softmax per token (threads 0..127), write assign^T ----
    if (tid < 128) {
        float l[128];
        #pragma unroll
        for (int j = 0; j < 128; j++) l[j] = sm[OFF_YS + j * YS + tid] + s_ba[j];
        float mx = l[0];
        #pragma unroll
        for (int j = 1; j < 128; j++) mx = fmaxf(mx, l[j]);
        float s = 0.0f;
        #pragma unroll
        for (int j = 0; j < 128; j++) { l[j] = __expf(l[j] - mx); s += l[j]; }
        const float inv = 1.0f / s;
        #pragma unroll
        for (int j = 0; j < 128; j++) sm[OFF_AS + j * YS + tid] = l[j] * inv;
    }
    __syncthreads();

    // ---- mass: row sums of assign^T (2 threads per cluster) ----
    {
        int cl = tid >> 1, half = tid & 1;
        float s = 0.0f;
        const float* row = &sm[OFF_AS + cl * YS + half * 64];
        #pragma unroll 16
        for (int i = 0; i < 64; i++) s += row[i];
        atomicAdd(&g_mass[b * Kk + cl], s);
    }

    // ---- stage 2: sq[128 tok, 64] = leaky(Y[:,128:192]+b1) @ W2^T ----
    const int m0 = w * 16;
    float acc2[8][4];
    #pragma unroll
    for (int nb = 0; nb < 8; nb++)
        #pragma unroll
        for (int q = 0; q < 4; q++) acc2[nb][q] = 0.0f;

    #pragma unroll
    for (int k8 = 0; k8 < 8; k8++) {
        const int kk = k8 * 8;
        uint32_t ah[4], al[4];
        {
            int base = OFF_YS + (128 + kk + tx) * YS + m0 + ty;
            float h0 = sm[base] + s_b1[kk + tx];
            float h1 = sm[base + 8] + s_b1[kk + tx];
            float h2 = sm[base + 4 * YS] + s_b1[kk + tx + 4];
            float h3 = sm[base + 4 * YS + 8] + s_b1[kk + tx + 4];
            h0 = (h0 >= 0.f) ? h0 : 0.01f * h0;
            h1 = (h1 >= 0.f) ? h1 : 0.01f * h1;
            h2 = (h2 >= 0.f) ? h2 : 0.01f * h2;
            h3 = (h3 >= 0.f) ? h3 : 0.01f * h3;
            split_tf(h0, ah[0], al[0]);
            split_tf(h1, ah[1], al[1]);
            split_tf(h2, ah[2], al[2]);
            split_tf(h3, ah[3], al[3]);
        }
        #pragma unroll
        for (int nb = 0; nb < 8; nb++) {
            uint32_t bh[2], bl[2];
            int bb = OFF_W2S + (nb * 8 + ty) * WS + kk + tx;
            split_tf(sm[bb],     bh[0], bl[0]);
            split_tf(sm[bb + 4], bh[1], bl[1]);
            mma8(acc2[nb], ah, bh);
            mma8(acc2[nb], ah, bl);
            mma8(acc2[nb], al, bh);
        }
    }
    // write sq^T [d][tok] (+b2)
    #pragma unroll
    for (int nb = 0; nb < 8; nb++) {
        int row = m0 + ty;              // token
        int col = nb * 8 + 2 * tx;      // d
        sm[OFF_BS3 + col * YS + row]           = acc2[nb][0] + s_b2[col];
        sm[OFF_BS3 + (col + 1) * YS + row]     = acc2[nb][1] + s_b2[col + 1];
        sm[OFF_BS3 + col * YS + row + 8]       = acc2[nb][2] + s_b2[col];
        sm[OFF_BS3 + (col + 1) * YS + row + 8] = acc2[nb][3] + s_b2[col + 1];
    }
    __syncthreads();

    // ---- stage 3: agg[128 cluster, 64] = assign^T @ sq  (K = 128 tokens) ----
    float acc3[8][4];
    #pragma unroll
    for (int nb = 0; nb < 8; nb++)
        #pragma unroll
        for (int q = 0; q < 4; q++) acc3[nb][q] = 0.0f;

    #pragma unroll
    for (int k8 = 0; k8 < 16; k8++) {
        const int kk = k8 * 8;
        uint32_t ah[4], al[4];
        {
            int base = OFF_AS + (m0 + ty) * YS + kk + tx;
            split_tf(sm[base],            ah[0], al[0]);
            split_tf(sm[base + 8 * YS],   ah[1], al[1]);
            split_tf(sm[base + 4],        ah[2], al[2]);
            split_tf(sm[base + 8 * YS + 4], ah[3], al[3]);
        }
        #pragma unroll
        for (int nb = 0; nb < 8; nb++) {
            uint32_t bh[2], bl[2];
            int bb = OFF_BS3 + (nb * 8 + ty) * YS + kk + tx;
            split_tf(sm[bb],     bh[0], bl[0]);
            split_tf(sm[bb + 4], bh[1], bl[1]);
            mma8(acc3[nb], ah, bh);
            mma8(acc3[nb], ah, bl);
            mma8(acc3[nb], al, bh);
        }
    }
    // ---- epilogue: atomics into g_agg ----
    {
        const size_t base0 = ((size_t)b * Kk + m0 + ty) * Dc;
        #pragma unroll
        for (int nb = 0; nb < 8; nb++) {
            int d0 = nb * 8 + 2 * tx;
            atomicAdd(&g_agg[base0 + d0],              acc3[nb][0]);
            atomicAdd(&g_agg[base0 + d0 + 1],          acc3[nb][1]);
            atomicAdd(&g_agg[base0 + 8 * Dc + d0],     acc3[nb][2]);
            atomicAdd(&g_agg[base0 + 8 * Dc + d0 + 1], acc3[nb][3]);
        }
    }
}

// ---------------- finalize: vlad = agg - mass*centroid, L2 normalize ----------------
__global__ void __launch_bounds__(256) k_final(const float* __restrict__ centroid,
                                               float* __restrict__ out) {
    __shared__ float red[256];
    __shared__ float s_inv;
    const int b = blockIdx.x;
    const int tid = threadIdx.x;

    float ss = 0.0f;
    for (int i = tid; i < Kk * Dc; i += 256) {
        int k = i >> 6;
        float v = g_agg[(size_t)b * (Kk * Dc) + i] - g_mass[b * Kk + k] * __ldg(&centroid[i]);
        out[(size_t)b * (Kk * Dc) + i] = v;
        ss += v * v;
    }
    red[tid] = ss;
    __syncthreads();
    #pragma unroll
    for (int s = 128; s > 0; s >>= 1) {
        if (tid < s) red[tid] += red[tid + s];
        __syncthreads();
    }
    if (tid == 0) {
        float n = sqrtf(red[0]);
        s_inv = 1.0f / fmaxf(n, 1e-12f);
    }
    __syncthreads();
    float inv = s_inv;
    for (int i = tid; i < Kk * Dc; i += 256) out[(size_t)b * (Kk * Dc) + i] *= inv;
}

// ---------------- launch ----------------
extern "C" void kernel_launch(void* const* d_in, const int* in_sizes, int n_in,
                              void* d_out, int out_size) {
    const float* X        = (const float*)d_in[0];
    const float* W1       = (const float*)d_in[1];
    const float* b1       = (const float*)d_in[2];
    const float* W2       = (const float*)d_in[3];
    const float* b2       = (const float*)d_in[4];
    const float* Wa       = (const float*)d_in[5];
    const float* ba       = (const float*)d_in[6];
    const float* centroid = (const float*)d_in[7];
    float* out = (float*)d_out;

    cudaFuncSetAttribute(k_fused, cudaFuncAttributeMaxDynamicSharedMemorySize,
                         SMEM_FLOATS * 4);

    k_init<<<1040, 256>>>();
    k_fused<<<1024, 256, SMEM_FLOATS * 4>>>(X, W1, b1, W2, b2, Wa, ba);
    k_final<<<Bb, 256>>>(centroid, out);
}

// round 6
// speedup vs baseline: 1.9698x; 1.3283x over previous
#include <cuda_runtime.h>
#include <cuda_bf16.h>
#include <math.h>
#include <stdint.h>

#define Bb 32
#define Nn 4096
#define Dd 256
#define Kk 128
#define Dc 64

// ---------------- device scratch ----------------
__device__ float g_agg[(size_t)Bb * Kk * Dc];
__device__ float g_mass[Bb * Kk];

// ---------------- smem word-offset layout (32-bit words) ----------------
// phase 1 (stage-1 GEMM):
#define OFF_XH   0        // X hi  [128 tok][132]  bf16x2 words
#define OFF_XL   16896    // X lo
#define OFF_WC_H 33792    // W chunk hi [192 row][36]
#define OFF_WC_L 40704    //            -> 47616
// phase 2 (aliases phase-1 regions, temporally disjoint):
#define OFF_Y    0        // Y fp32 col-major [192 col][132 tok] -> 25344
#define OFF_AT_H 25344    // assign^T hi [128 cl][68] -> 34048
#define OFF_AT_L 34048    //             -> 42752
#define OFF_H_H  42752    // h hi [128 tok][36] -> 47360
#define OFF_H_L  47360    //      -> 51968
#define OFF_SQ_H 42752    // sq^T hi [72 d][68] -> 47648 (aliases h after stage 2)
#define OFF_SQ_L 47648    //         -> 52544
// persistent:
#define OFF_W2_H 52544    // W2 hi [64 f][36] -> 54848
#define OFF_W2_L 54848    //       -> 57152
#define SMEM_WORDS 57152  // 228608 bytes

// ---------------- helpers ----------------
__device__ __forceinline__ void split2(float x, unsigned short& h, unsigned short& l) {
    __nv_bfloat16 hb = __float2bfloat16_rn(x);
    float lf = x - __bfloat162float(hb);
    h = __bfloat16_as_ushort(hb);
    l = __bfloat16_as_ushort(__float2bfloat16_rn(lf));
}
__device__ __forceinline__ void pack8(const float* v, uint4& H, uint4& L) {
    unsigned short h[8], l[8];
    #pragma unroll
    for (int i = 0; i < 8; i++) split2(v[i], h[i], l[i]);
    H.x = (uint32_t)h[0] | ((uint32_t)h[1] << 16);
    H.y = (uint32_t)h[2] | ((uint32_t)h[3] << 16);
    H.z = (uint32_t)h[4] | ((uint32_t)h[5] << 16);
    H.w = (uint32_t)h[6] | ((uint32_t)h[7] << 16);
    L.x = (uint32_t)l[0] | ((uint32_t)l[1] << 16);
    L.y = (uint32_t)l[2] | ((uint32_t)l[3] << 16);
    L.z = (uint32_t)l[4] | ((uint32_t)l[5] << 16);
    L.w = (uint32_t)l[6] | ((uint32_t)l[7] << 16);
}
// D(16x8,f32) += A(16x16 bf16 row) x B(16x8 bf16 col)
__device__ __forceinline__ void mma16(float* d, const uint32_t* a, const uint32_t* b) {
    asm volatile(
        "mma.sync.aligned.m16n8k16.row.col.f32.bf16.bf16.f32 "
        "{%0,%1,%2,%3}, {%4,%5,%6,%7}, {%8,%9}, {%0,%1,%2,%3};"
        : "+f"(d[0]), "+f"(d[1]), "+f"(d[2]), "+f"(d[3])
        : "r"(a[0]), "r"(a[1]), "r"(a[2]), "r"(a[3]), "r"(b[0]), "r"(b[1]));
}
__device__ __forceinline__ void st16s(uint32_t* smu, int word, int half, unsigned short v) {
    ((unsigned short*)&smu[word])[half] = v;
}

// ---------------- init ----------------
__global__ void __launch_bounds__(256) k_init() {
    int i = blockIdx.x * 256 + threadIdx.x;
    if (i < Bb * Kk * Dc) g_agg[i] = 0.0f;
    else if (i < Bb * Kk * Dc + Bb * Kk) g_mass[i - Bb * Kk * Dc] = 0.0f;
}

// ---------------- fused main kernel: one 128-token tile per block ----------------
__global__ void __launch_bounds__(256, 1) k_fused(
    const float* __restrict__ X,  const float* __restrict__ W1,
    const float* __restrict__ b1, const float* __restrict__ W2,
    const float* __restrict__ b2, const float* __restrict__ Wa,
    const float* __restrict__ ba)
{
    extern __shared__ float smf[];
    uint32_t* smu = (uint32_t*)smf;
    __shared__ float s_ba[128], s_b1[64], s_b2[64];

    const int tid  = threadIdx.x;
    const int w    = tid >> 5;
    const int lane = tid & 31;
    const int ty   = lane >> 2;        // groupID 0..7
    const int tx   = lane & 3;         // thread-in-group 0..3
    const int b    = blockIdx.x >> 5;
    const int n0t  = (blockIdx.x & 31) * 128;

    if (tid < 128) s_ba[tid] = ba[tid];
    else if (tid < 192) s_b1[tid - 128] = b1[tid - 128];
    else s_b2[tid - 192] = b2[tid - 192];

    // ---- fill: X tile (128x256) split -> bf16 hi/lo; W2 split ----
    {
        const float4* X4 = (const float4*)(X + (size_t)(b * Nn + n0t) * Dd);
        #pragma unroll
        for (int it = 0; it < 16; it++) {
            int idx = tid + it * 256;          // 0..4095 groups of 8 floats
            int row = idx >> 5, gg = idx & 31;
            float4 f0 = X4[row * 64 + gg * 2], f1 = X4[row * 64 + gg * 2 + 1];
            float v[8] = {f0.x, f0.y, f0.z, f0.w, f1.x, f1.y, f1.z, f1.w};
            uint4 H, L;
            pack8(v, H, L);
            *(uint4*)&smu[OFF_XH + row * 132 + gg * 4] = H;
            *(uint4*)&smu[OFF_XL + row * 132 + gg * 4] = L;
        }
        #pragma unroll
        for (int it = 0; it < 2; it++) {
            int idx = tid + it * 256;          // 0..511
            int row = idx >> 3, gg = idx & 7;
            const float* src = W2 + (size_t)row * 64 + gg * 8;
            float v[8] = {src[0], src[1], src[2], src[3], src[4], src[5], src[6], src[7]};
            uint4 H, L;
            pack8(v, H, L);
            *(uint4*)&smu[OFF_W2_H + row * 36 + gg * 4] = H;
            *(uint4*)&smu[OFF_W2_L + row * 36 + gg * 4] = L;
        }
    }

    // ---- stage 1: Y[128 tok, 192] = X @ [Wa;W1]^T  (K=256 in 4 chunks) ----
    const int wm = (w & 3) * 32;       // token block
    const int wn = (w >> 2) * 96;      // output-col block
    float acc1[2][12][4];
    #pragma unroll
    for (int mt = 0; mt < 2; mt++)
        #pragma unroll
        for (int nb = 0; nb < 12; nb++)
            #pragma unroll
            for (int q = 0; q < 4; q++) acc1[mt][nb][q] = 0.0f;

    for (int c = 0; c < 4; c++) {
        __syncthreads();
        #pragma unroll
        for (int it = 0; it < 6; it++) {
            int idx = tid + it * 256;          // 0..1535
            int row = idx >> 3, gg = idx & 7;
            const float* src = ((row < 128) ? (Wa + (size_t)row * Dd)
                                            : (W1 + (size_t)(row - 128) * Dd))
                               + c * 64 + gg * 8;
            float v[8] = {src[0], src[1], src[2], src[3], src[4], src[5], src[6], src[7]};
            uint4 H, L;
            pack8(v, H, L);
            *(uint4*)&smu[OFF_WC_H + row * 36 + gg * 4] = H;
            *(uint4*)&smu[OFF_WC_L + row * 36 + gg * 4] = L;
        }
        __syncthreads();

        #pragma unroll
        for (int s = 0; s < 4; s++) {
            const int kw = c * 32 + s * 8;     // word offset within X row
            uint32_t ah[2][4], al[2][4];
            #pragma unroll
            for (int mt = 0; mt < 2; mt++) {
                int base = (wm + mt * 16 + ty) * 132 + kw + tx;
                ah[mt][0] = smu[OFF_XH + base];
                ah[mt][1] = smu[OFF_XH + base + 8 * 132];
                ah[mt][2] = smu[OFF_XH + base + 4];
                ah[mt][3] = smu[OFF_XH + base + 8 * 132 + 4];
                al[mt][0] = smu[OFF_XL + base];
                al[mt][1] = smu[OFF_XL + base + 8 * 132];
                al[mt][2] = smu[OFF_XL + base + 4];
                al[mt][3] = smu[OFF_XL + base + 8 * 132 + 4];
            }
            uint32_t bh[12][2], bl[12][2];
            #pragma unroll
            for (int nb = 0; nb < 12; nb++) {
                int bb = (wn + nb * 8 + ty) * 36 + s * 8 + tx;
                bh[nb][0] = smu[OFF_WC_H + bb];
                bh[nb][1] = smu[OFF_WC_H + bb + 4];
                bl[nb][0] = smu[OFF_WC_L + bb];
                bl[nb][1] = smu[OFF_WC_L + bb + 4];
            }
            #pragma unroll
            for (int mt = 0; mt < 2; mt++)
                #pragma unroll
                for (int nb = 0; nb < 12; nb++) {
                    mma16(acc1[mt][nb], ah[mt], bh[nb]);
                    mma16(acc1[mt][nb], ah[mt], bl[nb]);
                    mma16(acc1[mt][nb], al[mt], bh[nb]);
                }
        }
    }
    __syncthreads();

    // ---- write Y column-major [col][tok] (fp32) ----
    #pragma unroll
    for (int mt = 0; mt < 2; mt++)
        #pragma unroll
        for (int nb = 0; nb < 12; nb++) {
            int row = wm + mt * 16 + ty;
            int col = wn + nb * 8 + 2 * tx;
            smf[OFF_Y + col * 132 + row]           = acc1[mt][nb][0];
            smf[OFF_Y + (col + 1) * 132 + row]     = acc1[mt][nb][1];
            smf[OFF_Y + col * 132 + row + 8]       = acc1[mt][nb][2];
            smf[OFF_Y + (col + 1) * 132 + row + 8] = acc1[mt][nb][3];
        }
    __syncthreads();

    // ---- softmax (threads 0..127) + h conversion (threads 128..255) ----
    if (tid < 128) {
        const int tok = tid;
        float mx = -1e30f;
        #pragma unroll 8
        for (int j = 0; j < 128; j++)
            mx = fmaxf(mx, smf[OFF_Y + j * 132 + tok] + s_ba[j]);
        float s = 0.0f;
        #pragma unroll 8
        for (int j = 0; j < 128; j++) {
            float e = __expf(smf[OFF_Y + j * 132 + tok] + s_ba[j] - mx);
            smf[OFF_Y + j * 132 + tok] = e;
            s += e;
        }
        const float inv = 1.0f / s;
        const int wrd = tok >> 1, hf = tok & 1;
        #pragma unroll 8
        for (int j = 0; j < 128; j++) {
            unsigned short hh, ll;
            split2(smf[OFF_Y + j * 132 + tok] * inv, hh, ll);
            st16s(smu, OFF_AT_H + j * 68 + wrd, hf, hh);
            st16s(smu, OFF_AT_L + j * 68 + wrd, hf, ll);
        }
    } else {
        const int tok = tid - 128;
        #pragma unroll
        for (int gg = 0; gg < 8; gg++) {
            float v[8];
            #pragma unroll
            for (int q = 0; q < 8; q++) {
                int e = gg * 8 + q;
                float h = smf[OFF_Y + (128 + e) * 132 + tok] + s_b1[e];
                v[q] = (h >= 0.0f) ? h : 0.01f * h;
            }
            uint4 H, L;
            pack8(v, H, L);
            *(uint4*)&smu[OFF_H_H + tok * 36 + gg * 4] = H;
            *(uint4*)&smu[OFF_H_L + tok * 36 + gg * 4] = L;
        }
    }
    __syncthreads();

    // ---- stage 2: sq[128 tok, 64] = h @ W2^T (K=64) ----
    const int m0 = w * 16;
    float acc2[8][4];
    #pragma unroll
    for (int nb = 0; nb < 8; nb++)
        #pragma unroll
        for (int q = 0; q < 4; q++) acc2[nb][q] = 0.0f;

    #pragma unroll
    for (int s = 0; s < 4; s++) {
        uint32_t ah[4], al[4];
        {
            int base = (m0 + ty) * 36 + s * 8 + tx;
            ah[0] = smu[OFF_H_H + base];
            ah[1] = smu[OFF_H_H + base + 8 * 36];
            ah[2] = smu[OFF_H_H + base + 4];
            ah[3] = smu[OFF_H_H + base + 8 * 36 + 4];
            al[0] = smu[OFF_H_L + base];
            al[1] = smu[OFF_H_L + base + 8 * 36];
            al[2] = smu[OFF_H_L + base + 4];
            al[3] = smu[OFF_H_L + base + 8 * 36 + 4];
        }
        #pragma unroll
        for (int nb = 0; nb < 8; nb++) {
            int bb = (nb * 8 + ty) * 36 + s * 8 + tx;
            uint32_t bh[2] = {smu[OFF_W2_H + bb], smu[OFF_W2_H + bb + 4]};
            uint32_t bl[2] = {smu[OFF_W2_L + bb], smu[OFF_W2_L + bb + 4]};
            mma16(acc2[nb], ah, bh);
            mma16(acc2[nb], ah, bl);
            mma16(acc2[nb], al, bh);
        }
    }
    __syncthreads();   // all stage-2 reads of h done before sq^T overwrites it

    // ---- write sq^T [d][tok] (+b2) as bf16 hi/lo; append ones row (d=64) ----
    #pragma unroll
    for (int nb = 0; nb < 8; nb++)
        #pragma unroll
        for (int q = 0; q < 4; q++) {
            int row = m0 + ty + ((q >> 1) << 3);      // token
            int col = nb * 8 + 2 * tx + (q & 1);      // d
            unsigned short hh, ll;
            split2(acc2[nb][q] + s_b2[col], hh, ll);
            st16s(smu, OFF_SQ_H + col * 68 + (row >> 1), row & 1, hh);
            st16s(smu, OFF_SQ_L + col * 68 + (row >> 1), row & 1, ll);
        }
    if (tid < 128) {
        const int tok = tid, wrd = tok >> 1, hf = tok & 1;
        st16s(smu, OFF_SQ_H + 64 * 68 + wrd, hf, (unsigned short)0x3F80);  // 1.0bf16
        st16s(smu, OFF_SQ_L + 64 * 68 + wrd, hf, 0);
        #pragma unroll
        for (int rr = 65; rr < 72; rr++) {
            st16s(smu, OFF_SQ_H + rr * 68 + wrd, hf, 0);
            st16s(smu, OFF_SQ_L + rr * 68 + wrd, hf, 0);
        }
    }
    __syncthreads();

    // ---- stage 3: D3[128 cl, 72] = assign^T @ [sq | 1]  (K=128 tokens) ----
    float acc3[9][4];
    #pragma unroll
    for (int nb = 0; nb < 9; nb++)
        #pragma unroll
        for (int q = 0; q < 4; q++) acc3[nb][q] = 0.0f;

    #pragma unroll
    for (int s = 0; s < 8; s++) {
        uint32_t ah[4], al[4];
        {
            int base = (m0 + ty) * 68 + s * 8 + tx;
            ah[0] = smu[OFF_AT_H + base];
            ah[1] = smu[OFF_AT_H + base + 8 * 68];
            ah[2] = smu[OFF_AT_H + base + 4];
            ah[3] = smu[OFF_AT_H + base + 8 * 68 + 4];
            al[0] = smu[OFF_AT_L + base];
            al[1] = smu[OFF_AT_L + base + 8 * 68];
            al[2] = smu[OFF_AT_L + base + 4];
            al[3] = smu[OFF_AT_L + base + 8 * 68 + 4];
        }
        #pragma unroll
        for (int nb = 0; nb < 9; nb++) {
            int bb = (nb * 8 + ty) * 68 + s * 8 + tx;
            uint32_t bh[2] = {smu[OFF_SQ_H + bb], smu[OFF_SQ_H + bb + 4]};
            uint32_t bl[2] = {smu[OFF_SQ_L + bb], smu[OFF_SQ_L + bb + 4]};
            mma16(acc3[nb], ah, bh);
            mma16(acc3[nb], ah, bl);
            mma16(acc3[nb], al, bh);
        }
    }

    // ---- epilogue: atomics ----
    {
        const size_t base0 = ((size_t)b * Kk + m0 + ty) * Dc;
        #pragma unroll
        for (int nb = 0; nb < 8; nb++) {
            int d0 = nb * 8 + 2 * tx;
            atomicAdd(&g_agg[base0 + d0],              acc3[nb][0]);
            atomicAdd(&g_agg[base0 + d0 + 1],          acc3[nb][1]);
            atomicAdd(&g_agg[base0 + 8 * Dc + d0],     acc3[nb][2]);
            atomicAdd(&g_agg[base0 + 8 * Dc + d0 + 1], acc3[nb][3]);
        }
        if (tx == 0) {   // column 64 = mass
            atomicAdd(&g_mass[b * Kk + m0 + ty],     acc3[8][0]);
            atomicAdd(&g_mass[b * Kk + m0 + ty + 8], acc3[8][2]);
        }
    }
}

// ---------------- finalize: vlad = agg - mass*centroid, L2 normalize ----------------
__global__ void __launch_bounds__(256) k_final(const float* __restrict__ centroid,
                                               float* __restrict__ out) {
    __shared__ float red[256];
    __shared__ float s_inv;
    const int b = blockIdx.x;
    const int tid = threadIdx.x;

    float ss = 0.0f;
    for (int i = tid; i < Kk * Dc; i += 256) {
        int k = i >> 6;
        float v = g_agg[(size_t)b * (Kk * Dc) + i] - g_mass[b * Kk + k] * __ldg(&centroid[i]);
        out[(size_t)b * (Kk * Dc) + i] = v;
        ss += v * v;
    }
    red[tid] = ss;
    __syncthreads();
    #pragma unroll
    for (int s = 128; s > 0; s >>= 1) {
        if (tid < s) red[tid] += red[tid + s];
        __syncthreads();
    }
    if (tid == 0) {
        float n = sqrtf(red[0]);
        s_inv = 1.0f / fmaxf(n, 1e-12f);
    }
    __syncthreads();
    float inv = s_inv;
    for (int i = tid; i < Kk * Dc; i += 256) out[(size_t)b * (Kk * Dc) + i] *= inv;
}

// ---------------- launch ----------------
extern "C" void kernel_launch(void* const* d_in, const int* in_sizes, int n_in,
                              void* d_out, int out_size) {
    const float* X        = (const float*)d_in[0];
    const float* W1       = (const float*)d_in[1];
    const float* b1       = (const float*)d_in[2];
    const float* W2       = (const float*)d_in[3];
    const float* b2       = (const float*)d_in[4];
    const float* Wa       = (const float*)d_in[5];
    const float* ba       = (const float*)d_in[6];
    const float* centroid = (const float*)d_in[7];
    float* out = (float*)d_out;

    cudaFuncSetAttribute(k_fused, cudaFuncAttributeMaxDynamicSharedMemorySize,
                         SMEM_WORDS * 4);

    k_init<<<1040, 256>>>();
    k_fused<<<1024, 256, SMEM_WORDS * 4>>>(X, W1, b1, W2, b2, Wa, ba);
    k_final<<<Bb, 256>>>(centroid, out);
}

// round 7
// speedup vs baseline: 2.1136x; 1.0730x over previous
#include <cuda_runtime.h>
#include <cuda_bf16.h>
#include <math.h>
#include <stdint.h>

#define Bb 32
#define Nn 4096
#define Dd 256
#define Kk 128
#define Dc 64

// ---------------- device scratch ----------------
__device__ float g_agg[(size_t)Bb * Kk * Dc];
__device__ float g_mass[Bb * Kk];

// ---------------- smem word-offset layout (32-bit words) ----------------
#define OFF_XH   0        // X hi  [128 tok][132]
#define OFF_XL   16896
#define OFF_WC_H 33792    // W chunk hi [192 row][36]
#define OFF_WC_L 40704
#define OFF_Y    0        // Y fp32 col-major [192 col][132 tok]
#define OFF_AT_H 25344    // assign^T hi [128 cl][68]
#define OFF_AT_L 34048
#define OFF_H_H  42752    // h hi [128 tok][36]
#define OFF_H_L  47360
#define OFF_SQ_H 42752    // sq^T hi [72 d][68] (aliases h after stage 2)
#define OFF_SQ_L 47648
#define OFF_W2_H 52544    // W2 hi [64 f][36]
#define OFF_W2_L 54848
#define SMEM_WORDS 57152  // 228608 bytes

// ---------------- helpers ----------------
__device__ __forceinline__ void split2(float x, unsigned short& h, unsigned short& l) {
    __nv_bfloat16 hb = __float2bfloat16_rn(x);
    float lf = x - __bfloat162float(hb);
    h = __bfloat16_as_ushort(hb);
    l = __bfloat16_as_ushort(__float2bfloat16_rn(lf));
}
__device__ __forceinline__ void pack8(const float* v, uint4& H, uint4& L) {
    unsigned short h[8], l[8];
    #pragma unroll
    for (int i = 0; i < 8; i++) split2(v[i], h[i], l[i]);
    H.x = (uint32_t)h[0] | ((uint32_t)h[1] << 16);
    H.y = (uint32_t)h[2] | ((uint32_t)h[3] << 16);
    H.z = (uint32_t)h[4] | ((uint32_t)h[5] << 16);
    H.w = (uint32_t)h[6] | ((uint32_t)h[7] << 16);
    L.x = (uint32_t)l[0] | ((uint32_t)l[1] << 16);
    L.y = (uint32_t)l[2] | ((uint32_t)l[3] << 16);
    L.z = (uint32_t)l[4] | ((uint32_t)l[5] << 16);
    L.w = (uint32_t)l[6] | ((uint32_t)l[7] << 16);
}
__device__ __forceinline__ void mma16(float* d, const uint32_t* a, const uint32_t* b) {
    asm volatile(
        "mma.sync.aligned.m16n8k16.row.col.f32.bf16.bf16.f32 "
        "{%0,%1,%2,%3}, {%4,%5,%6,%7}, {%8,%9}, {%0,%1,%2,%3};"
        : "+f"(d[0]), "+f"(d[1]), "+f"(d[2]), "+f"(d[3])
        : "r"(a[0]), "r"(a[1]), "r"(a[2]), "r"(a[3]), "r"(b[0]), "r"(b[1]));
}
__device__ __forceinline__ void st16s(uint32_t* smu, int word, int half, unsigned short v) {
    ((unsigned short*)&smu[word])[half] = v;
}
__device__ __forceinline__ uint32_t sptr(const void* p) {
    return (uint32_t)__cvta_generic_to_shared(p);
}
#define LDSM4(R0, R1, R2, R3, A) \
    asm volatile("ldmatrix.sync.aligned.m8n8.x4.shared.b16 {%0,%1,%2,%3}, [%4];" \
                 : "=r"(R0), "=r"(R1), "=r"(R2), "=r"(R3) : "r"(A))
#define LDSM2(R0, R1, A) \
    asm volatile("ldmatrix.sync.aligned.m8n8.x2.shared.b16 {%0,%1}, [%2];" \
                 : "=r"(R0), "=r"(R1) : "r"(A))

// ---------------- init ----------------
__global__ void __launch_bounds__(256) k_init() {
    int i = blockIdx.x * 256 + threadIdx.x;
    if (i < Bb * Kk * Dc) g_agg[i] = 0.0f;
    else if (i < Bb * Kk * Dc + Bb * Kk) g_mass[i - Bb * Kk * Dc] = 0.0f;
}

// ---------------- fused main kernel: one 128-token tile per block ----------------
__global__ void __launch_bounds__(256, 1) k_fused(
    const float* __restrict__ X,  const float* __restrict__ W1,
    const float* __restrict__ b1, const float* __restrict__ W2,
    const float* __restrict__ b2, const float* __restrict__ Wa,
    const float* __restrict__ ba)
{
    extern __shared__ float smf[];
    uint32_t* smu = (uint32_t*)smf;
    __shared__ float s_ba[128], s_b1[64], s_b2[64];

    const int tid  = threadIdx.x;
    const int w    = tid >> 5;
    const int lane = tid & 31;
    const int ty   = lane >> 2;
    const int tx   = lane & 3;
    const int b    = blockIdx.x >> 5;
    const int n0t  = (blockIdx.x & 31) * 128;

    // ldmatrix lane geometry
    const int matq = lane >> 3, rowq = lane & 7;
    const int mrow  = (matq & 1) * 8 + rowq;    // A-type: m split on mat bit0
    const int acolw = (matq >> 1) * 4;          // A-type k-word offset
    const int nrow  = (matq >> 1) * 8 + rowq;   // B-type: n split on mat bit1
    const int bcolw = (matq & 1) * 4;           // B-type k-word offset

    if (tid < 128) s_ba[tid] = ba[tid];
    else if (tid < 192) s_b1[tid - 128] = b1[tid - 128];
    else s_b2[tid - 192] = b2[tid - 192];

    // ---- fill: X tile (128x256) split -> bf16 hi/lo; W2 split ----
    {
        const float4* X4 = (const float4*)(X + (size_t)(b * Nn + n0t) * Dd);
        #pragma unroll
        for (int it = 0; it < 16; it++) {
            int idx = tid + it * 256;
            int row = idx >> 5, gg = idx & 31;
            float4 f0 = X4[row * 64 + gg * 2], f1 = X4[row * 64 + gg * 2 + 1];
            float v[8] = {f0.x, f0.y, f0.z, f0.w, f1.x, f1.y, f1.z, f1.w};
            uint4 H, L;
            pack8(v, H, L);
            *(uint4*)&smu[OFF_XH + row * 132 + gg * 4] = H;
            *(uint4*)&smu[OFF_XL + row * 132 + gg * 4] = L;
        }
        #pragma unroll
        for (int it = 0; it < 2; it++) {
            int idx = tid + it * 256;
            int row = idx >> 3, gg = idx & 7;
            const float* src = W2 + (size_t)row * 64 + gg * 8;
            float v[8] = {src[0], src[1], src[2], src[3], src[4], src[5], src[6], src[7]};
            uint4 H, L;
            pack8(v, H, L);
            *(uint4*)&smu[OFF_W2_H + row * 36 + gg * 4] = H;
            *(uint4*)&smu[OFF_W2_L + row * 36 + gg * 4] = L;
        }
    }

    // ---- stage 1: Y[128 tok, 192] = X @ [Wa;W1]^T  (K=256 in 4 chunks) ----
    const int wm = (w & 3) * 32;
    const int wn = (w >> 2) * 96;
    float acc1[2][12][4];
    #pragma unroll
    for (int mt = 0; mt < 2; mt++)
        #pragma unroll
        for (int nb = 0; nb < 12; nb++)
            #pragma unroll
            for (int q = 0; q < 4; q++) acc1[mt][nb][q] = 0.0f;

    uint32_t aAh[2], aAl[2], aBh[6], aBl[6];
    #pragma unroll
    for (int mt = 0; mt < 2; mt++) {
        aAh[mt] = sptr(&smu[OFF_XH + (wm + mt * 16 + mrow) * 132 + acolw]);
        aAl[mt] = sptr(&smu[OFF_XL + (wm + mt * 16 + mrow) * 132 + acolw]);
    }
    #pragma unroll
    for (int pp = 0; pp < 6; pp++) {
        aBh[pp] = sptr(&smu[OFF_WC_H + (wn + pp * 16 + nrow) * 36 + bcolw]);
        aBl[pp] = sptr(&smu[OFF_WC_L + (wn + pp * 16 + nrow) * 36 + bcolw]);
    }

    for (int c = 0; c < 4; c++) {
        __syncthreads();
        #pragma unroll
        for (int it = 0; it < 6; it++) {
            int idx = tid + it * 256;
            int row = idx >> 3, gg = idx & 7;
            const float* src = ((row < 128) ? (Wa + (size_t)row * Dd)
                                            : (W1 + (size_t)(row - 128) * Dd))
                               + c * 64 + gg * 8;
            float v[8] = {src[0], src[1], src[2], src[3], src[4], src[5], src[6], src[7]};
            uint4 H, L;
            pack8(v, H, L);
            *(uint4*)&smu[OFF_WC_H + row * 36 + gg * 4] = H;
            *(uint4*)&smu[OFF_WC_L + row * 36 + gg * 4] = L;
        }
        __syncthreads();

        #pragma unroll
        for (int s = 0; s < 4; s++) {
            const uint32_t offA = (uint32_t)(c * 32 + s * 8) * 4;
            const uint32_t offB = (uint32_t)(s * 8) * 4;
            uint32_t ah[2][4], al[2][4];
            LDSM4(ah[0][0], ah[0][1], ah[0][2], ah[0][3], aAh[0] + offA);
            LDSM4(ah[1][0], ah[1][1], ah[1][2], ah[1][3], aAh[1] + offA);
            LDSM4(al[0][0], al[0][1], al[0][2], al[0][3], aAl[0] + offA);
            LDSM4(al[1][0], al[1][1], al[1][2], al[1][3], aAl[1] + offA);
            #pragma unroll
            for (int pp = 0; pp < 6; pp++) {
                uint32_t bh[4], bl[4];
                LDSM4(bh[0], bh[1], bh[2], bh[3], aBh[pp] + offB);
                LDSM4(bl[0], bl[1], bl[2], bl[3], aBl[pp] + offB);
                #pragma unroll
                for (int e = 0; e < 2; e++) {
                    const int nb = pp * 2 + e;
                    #pragma unroll
                    for (int mt = 0; mt < 2; mt++) {
                        mma16(acc1[mt][nb], ah[mt], bh + e * 2);
                        mma16(acc1[mt][nb], ah[mt], bl + e * 2);
                        mma16(acc1[mt][nb], al[mt], bh + e * 2);
                    }
                }
            }
        }
    }
    __syncthreads();

    // ---- write Y column-major [col][tok] (fp32) ----
    #pragma unroll
    for (int mt = 0; mt < 2; mt++)
        #pragma unroll
        for (int nb = 0; nb < 12; nb++) {
            int row = wm + mt * 16 + ty;
            int col = wn + nb * 8 + 2 * tx;
            smf[OFF_Y + col * 132 + row]           = acc1[mt][nb][0];
            smf[OFF_Y + (col + 1) * 132 + row]     = acc1[mt][nb][1];
            smf[OFF_Y + col * 132 + row + 8]       = acc1[mt][nb][2];
            smf[OFF_Y + (col + 1) * 132 + row + 8] = acc1[mt][nb][3];
        }
    __syncthreads();

    // ---- softmax: 2 threads per token; then h-convert: 2 threads per token ----
    {
        const int tok = tid >> 1;
        const int j0 = (tid & 1) * 64;
        float mx = -1e30f;
        #pragma unroll 8
        for (int j = j0; j < j0 + 64; j++)
            mx = fmaxf(mx, smf[OFF_Y + j * 132 + tok] + s_ba[j]);
        mx = fmaxf(mx, __shfl_xor_sync(0xFFFFFFFFu, mx, 1));
        float ssum = 0.0f;
        #pragma unroll 8
        for (int j = j0; j < j0 + 64; j++) {
            float e = __expf(smf[OFF_Y + j * 132 + tok] + s_ba[j] - mx);
            smf[OFF_Y + j * 132 + tok] = e;
            ssum += e;
        }
        ssum += __shfl_xor_sync(0xFFFFFFFFu, ssum, 1);
        const float inv = 1.0f / ssum;
        const int wrd = tok >> 1, hf = tok & 1;
        #pragma unroll 8
        for (int j = j0; j < j0 + 64; j++) {
            unsigned short hh, ll;
            split2(smf[OFF_Y + j * 132 + tok] * inv, hh, ll);
            st16s(smu, OFF_AT_H + j * 68 + wrd, hf, hh);
            st16s(smu, OFF_AT_L + j * 68 + wrd, hf, ll);
        }
        // h: this thread handles e-range (tid&1)*32..+31 of its token
        #pragma unroll
        for (int g4 = 0; g4 < 4; g4++) {
            const int gg = (tid & 1) * 4 + g4;
            float v[8];
            #pragma unroll
            for (int q = 0; q < 8; q++) {
                int e = gg * 8 + q;
                float h = smf[OFF_Y + (128 + e) * 132 + tok] + s_b1[e];
                v[q] = (h >= 0.0f) ? h : 0.01f * h;
            }
            uint4 H, L;
            pack8(v, H, L);
            *(uint4*)&smu[OFF_H_H + tok * 36 + gg * 4] = H;
            *(uint4*)&smu[OFF_H_L + tok * 36 + gg * 4] = L;
        }
    }
    __syncthreads();

    // ---- stage 2: sq[128 tok, 64] = h @ W2^T (K=64) ----
    const int m0 = w * 16;
    float acc2[8][4];
    #pragma unroll
    for (int nb = 0; nb < 8; nb++)
        #pragma unroll
        for (int q = 0; q < 4; q++) acc2[nb][q] = 0.0f;

    {
        const uint32_t aH2h = sptr(&smu[OFF_H_H + (m0 + mrow) * 36 + acolw]);
        const uint32_t aH2l = sptr(&smu[OFF_H_L + (m0 + mrow) * 36 + acolw]);
        uint32_t aW2h[4], aW2l[4];
        #pragma unroll
        for (int pp = 0; pp < 4; pp++) {
            aW2h[pp] = sptr(&smu[OFF_W2_H + (pp * 16 + nrow) * 36 + bcolw]);
            aW2l[pp] = sptr(&smu[OFF_W2_L + (pp * 16 + nrow) * 36 + bcolw]);
        }
        #pragma unroll
        for (int s = 0; s < 4; s++) {
            const uint32_t off = (uint32_t)(s * 8) * 4;
            uint32_t ah[4], al[4];
            LDSM4(ah[0], ah[1], ah[2], ah[3], aH2h + off);
            LDSM4(al[0], al[1], al[2], al[3], aH2l + off);
            #pragma unroll
            for (int pp = 0; pp < 4; pp++) {
                uint32_t bh[4], bl[4];
                LDSM4(bh[0], bh[1], bh[2], bh[3], aW2h[pp] + off);
                LDSM4(bl[0], bl[1], bl[2], bl[3], aW2l[pp] + off);
                #pragma unroll
                for (int e = 0; e < 2; e++) {
                    const int nb = pp * 2 + e;
                    mma16(acc2[nb], ah, bh + e * 2);
                    mma16(acc2[nb], ah, bl + e * 2);
                    mma16(acc2[nb], al, bh + e * 2);
                }
            }
        }
    }
    __syncthreads();   // all stage-2 reads of h done before sq^T overwrites it

    // ---- write sq^T [d][tok] (+b2) as bf16 hi/lo; append ones row (d=64) ----
    #pragma unroll
    for (int nb = 0; nb < 8; nb++)
        #pragma unroll
        for (int q = 0; q < 4; q++) {
            int row = m0 + ty + ((q >> 1) << 3);      // token
            int col = nb * 8 + 2 * tx + (q & 1);      // d
            unsigned short hh, ll;
            split2(acc2[nb][q] + s_b2[col], hh, ll);
            st16s(smu, OFF_SQ_H + col * 68 + (row >> 1), row & 1, hh);
            st16s(smu, OFF_SQ_L + col * 68 + (row >> 1), row & 1, ll);
        }
    if (tid < 128) {
        const int tok = tid, wrd = tok >> 1, hf = tok & 1;
        st16s(smu, OFF_SQ_H + 64 * 68 + wrd, hf, (unsigned short)0x3F80);
        st16s(smu, OFF_SQ_L + 64 * 68 + wrd, hf, 0);
        #pragma unroll
        for (int rr = 65; rr < 72; rr++) {
            st16s(smu, OFF_SQ_H + rr * 68 + wrd, hf, 0);
            st16s(smu, OFF_SQ_L + rr * 68 + wrd, hf, 0);
        }
    }
    __syncthreads();

    // ---- stage 3: D3[128 cl, 72] = assign^T @ [sq | 1]  (K=128 tokens) ----
    float acc3[9][4];
    #pragma unroll
    for (int nb = 0; nb < 9; nb++)
        #pragma unroll
        for (int q = 0; q < 4; q++) acc3[nb][q] = 0.0f;

    {
        const uint32_t aA3h = sptr(&smu[OFF_AT_H + (m0 + mrow) * 68 + acolw]);
        const uint32_t aA3l = sptr(&smu[OFF_AT_L + (m0 + mrow) * 68 + acolw]);
        uint32_t aB3h[4], aB3l[4];
        #pragma unroll
        for (int pp = 0; pp < 4; pp++) {
            aB3h[pp] = sptr(&smu[OFF_SQ_H + (pp * 16 + nrow) * 68 + bcolw]);
            aB3l[pp] = sptr(&smu[OFF_SQ_L + (pp * 16 + nrow) * 68 + bcolw]);
        }
        const int mat2 = (lane >> 3) & 1;
        const uint32_t aB9h = sptr(&smu[OFF_SQ_H + (64 + rowq) * 68 + mat2 * 4]);
        const uint32_t aB9l = sptr(&smu[OFF_SQ_L + (64 + rowq) * 68 + mat2 * 4]);

        #pragma unroll
        for (int s = 0; s < 8; s++) {
            const uint32_t off = (uint32_t)(s * 8) * 4;
            uint32_t ah[4], al[4];
            LDSM4(ah[0], ah[1], ah[2], ah[3], aA3h + off);
            LDSM4(al[0], al[1], al[2], al[3], aA3l + off);
            #pragma unroll
            for (int pp = 0; pp < 4; pp++) {
                uint32_t bh[4], bl[4];
                LDSM4(bh[0], bh[1], bh[2], bh[3], aB3h[pp] + off);
                LDSM4(bl[0], bl[1], bl[2], bl[3], aB3l[pp] + off);
                #pragma unroll
                for (int e = 0; e < 2; e++) {
                    const int nb = pp * 2 + e;
                    mma16(acc3[nb], ah, bh + e * 2);
                    mma16(acc3[nb], ah, bl + e * 2);
                    mma16(acc3[nb], al, bh + e * 2);
                }
            }
            {
                uint32_t b9h[2], b9l[2];
                LDSM2(b9h[0], b9h[1], aB9h + off);
                LDSM2(b9l[0], b9l[1], aB9l + off);
                mma16(acc3[8], ah, b9h);
                mma16(acc3[8], ah, b9l);
                mma16(acc3[8], al, b9h);
            }
        }
    }

    // ---- epilogue: atomics ----
    {
        const size_t base0 = ((size_t)b * Kk + m0 + ty) * Dc;
        #pragma unroll
        for (int nb = 0; nb < 8; nb++) {
            int d0 = nb * 8 + 2 * tx;
            atomicAdd(&g_agg[base0 + d0],              acc3[nb][0]);
            atomicAdd(&g_agg[base0 + d0 + 1],          acc3[nb][1]);
            atomicAdd(&g_agg[base0 + 8 * Dc + d0],     acc3[nb][2]);
            atomicAdd(&g_agg[base0 + 8 * Dc + d0 + 1], acc3[nb][3]);
        }
        if (tx == 0) {
            atomicAdd(&g_mass[b * Kk + m0 + ty],     acc3[8][0]);
            atomicAdd(&g_mass[b * Kk + m0 + ty + 8], acc3[8][2]);
        }
    }
}

// ---------------- finalize: vlad = agg - mass*centroid, L2 normalize ----------------
__global__ void __launch_bounds__(256) k_final(const float* __restrict__ centroid,
                                               float* __restrict__ out) {
    __shared__ float red[256];
    __shared__ float s_inv;
    const int b = blockIdx.x;
    const int tid = threadIdx.x;

    float ss = 0.0f;
    for (int i = tid; i < Kk * Dc; i += 256) {
        int k = i >> 6;
        float v = g_agg[(size_t)b * (Kk * Dc) + i] - g_mass[b * Kk + k] * __ldg(&centroid[i]);
        out[(size_t)b * (Kk * Dc) + i] = v;
        ss += v * v;
    }
    red[tid] = ss;
    __syncthreads();
    #pragma unroll
    for (int s = 128; s > 0; s >>= 1) {
        if (tid < s) red[tid] += red[tid + s];
        __syncthreads();
    }
    if (tid == 0) {
        float n = sqrtf(red[0]);
        s_inv = 1.0f / fmaxf(n, 1e-12f);
    }
    __syncthreads();
    float inv = s_inv;
    for (int i = tid; i < Kk * Dc; i += 256) out[(size_t)b * (Kk * Dc) + i] *= inv;
}

// ---------------- launch ----------------
extern "C" void kernel_launch(void* const* d_in, const int* in_sizes, int n_in,
                              void* d_out, int out_size) {
    const float* X        = (const float*)d_in[0];
    const float* W1       = (const float*)d_in[1];
    const float* b1       = (const float*)d_in[2];
    const float* W2       = (const float*)d_in[3];
    const float* b2       = (const float*)d_in[4];
    const float* Wa       = (const float*)d_in[5];
    const float* ba       = (const float*)d_in[6];
    const float* centroid = (const float*)d_in[7];
    float* out = (float*)d_out;

    cudaFuncSetAttribute(k_fused, cudaFuncAttributeMaxDynamicSharedMemorySize,
                         SMEM_WORDS * 4);

    k_init<<<1040, 256>>>();
    k_fused<<<1024, 256, SMEM_WORDS * 4>>>(X, W1, b1, W2, b2, Wa, ba);
    k_final<<<Bb, 256>>>(centroid, out);
}